// round 1
// baseline (speedup 1.0000x reference)
#include <cuda_runtime.h>
#include <math.h>

// Problem constants
#define B_TOT 256
#define AIN   8
#define MUL   1024
#define NK    20
#define NO    16

// Persistent scratch (device globals; allocation-free)
__device__ float g_c[NK * MUL];              // routing coefficients c[k][m]
__device__ float g_b[NK * MUL];              // logits b[k][m]
__device__ float g_bpart[8 * NK * MUL];      // per-b-slice partial agreement sums
__device__ float g_wv[B_TOT * NK * AIN];     // wv[b][k][a] = sum_o W[k,o,a]*v[b,k,o]

// ---------------------------------------------------------------------------
// Fused per-batch kernel: (softmax coeffs read from g_c or uniform),
// y = c^T x, s = W y, v = squash(s), wv = W^T v  — all per 2 batches / block.
// ---------------------------------------------------------------------------
#define BPB        2
#define F_THREADS  640          // == BPB*NK*NO exactly
#define PLANE      1032         // padded plane stride (conflict-free banks)
#define XS_PER_B   (AIN * PLANE)

#define WARP_RED_SUM(v)                                   \
  do {                                                    \
    v += __shfl_xor_sync(0xffffffffu, v, 16);             \
    v += __shfl_xor_sync(0xffffffffu, v, 8);              \
    v += __shfl_xor_sync(0xffffffffu, v, 4);              \
    v += __shfl_xor_sync(0xffffffffu, v, 2);              \
    v += __shfl_xor_sync(0xffffffffu, v, 1);              \
  } while (0)

__global__ void __launch_bounds__(F_THREADS)
fused_kernel(const float* __restrict__ x, const float* __restrict__ W,
             float* __restrict__ out, int uniform_c, int final_iter)
{
    extern __shared__ float sm[];
    float* xs  = sm;                          // [BPB][AIN][PLANE]
    float* wsm = xs  + BPB * XS_PER_B;        // [NK*NO*AIN] = 2560
    float* ysm = wsm + NK * NO * AIN;         // [BPB][NK][AIN] = 320
    float* ssm = ysm + BPB * NK * AIN;        // [BPB][NK][NO]  = 640 (s, then v)
    float* csm = ssm + BPB * NK * NO;         // [BPB][NO]      = 32

    const int tid = threadIdx.x;
    const int b0  = blockIdx.x * BPB;

    // Stage x for the 2 batches, plane-major: xs[bl][a][m]
    for (int i = tid; i < BPB * MUL * AIN; i += F_THREADS) {
        int bl = i >> 13;
        int r  = i & 8191;
        float v = x[(size_t)(b0 + bl) * (MUL * AIN) + r];
        xs[bl * XS_PER_B + (r & 7) * PLANE + (r >> 3)] = v;
    }
    for (int i = tid; i < NK * NO * AIN; i += F_THREADS) wsm[i] = W[i];
    __syncthreads();

    // ---- y phase: warp w owns class k = w ----
    {
        const int w = tid >> 5, lane = tid & 31;
        const int k = w;                      // 20 warps == 20 classes
        const float* crow = g_c + k * MUL;
        for (int bl = 0; bl < BPB; bl++) {
            const float* xb = xs + bl * XS_PER_B;
            float a0 = 0.f, a1 = 0.f, a2 = 0.f, a3 = 0.f;
            float a4 = 0.f, a5 = 0.f, a6 = 0.f, a7 = 0.f;
            #pragma unroll 4
            for (int j = 0; j < 32; j++) {
                int m = j * 32 + lane;
                float cv = uniform_c ? 9.765625e-4f : crow[m];
                a0 += cv * xb[m];
                a1 += cv * xb[m + PLANE];
                a2 += cv * xb[m + 2 * PLANE];
                a3 += cv * xb[m + 3 * PLANE];
                a4 += cv * xb[m + 4 * PLANE];
                a5 += cv * xb[m + 5 * PLANE];
                a6 += cv * xb[m + 6 * PLANE];
                a7 += cv * xb[m + 7 * PLANE];
            }
            WARP_RED_SUM(a0); WARP_RED_SUM(a1); WARP_RED_SUM(a2); WARP_RED_SUM(a3);
            WARP_RED_SUM(a4); WARP_RED_SUM(a5); WARP_RED_SUM(a6); WARP_RED_SUM(a7);
            if (lane == 0) {
                float* yb = ysm + (bl * NK + k) * AIN;
                yb[0] = a0; yb[1] = a1; yb[2] = a2; yb[3] = a3;
                yb[4] = a4; yb[5] = a5; yb[6] = a6; yb[7] = a7;
            }
        }
    }
    __syncthreads();

    // ---- s phase: tid -> (bl, k, o) ----
    const int bl = tid / (NK * NO);
    const int r  = tid % (NK * NO);
    const int k  = r / NO;
    const int o  = r % NO;
    {
        const float* wk = wsm + (k * NO + o) * AIN;
        const float* yk = ysm + (bl * NK + k) * AIN;
        float s = 0.f;
        #pragma unroll
        for (int a = 0; a < AIN; a++) s += wk[a] * yk[a];
        ssm[tid] = s;                         // layout matches [bl][k][o]
        __syncthreads();

        // squash coefficient: sum over classes (axis=1 in the reference!)
        if (tid < BPB * NO) {
            int bb = tid / NO, oo = tid % NO;
            float msq = 0.f;
            #pragma unroll
            for (int kk = 0; kk < NK; kk++) {
                float t = ssm[bb * NK * NO + kk * NO + oo];
                msq += t * t;
            }
            csm[tid] = msq / ((1.f + msq) * sqrtf(msq));
        }
        __syncthreads();

        float v = csm[bl * NO + o] * s;
        if (final_iter) {
            out[(size_t)(b0 + bl) * (NK * NO) + r] = v;   // perfectly coalesced
        }
        ssm[tid] = v;                         // overwrite s with v
    }
    __syncthreads();

    // ---- wv phase (not needed on final iteration) ----
    if (!final_iter && tid < BPB * NK * AIN) {
        int bb = tid / (NK * AIN);
        int rr = tid % (NK * AIN);
        int kk = rr / AIN, aa = rr % AIN;
        float acc = 0.f;
        #pragma unroll
        for (int oo = 0; oo < NO; oo++)
            acc += wsm[(kk * NO + oo) * AIN + aa] * ssm[bb * NK * NO + kk * NO + oo];
        g_wv[(size_t)(b0 + bb) * (NK * AIN) + rr] = acc;
    }
}

// ---------------------------------------------------------------------------
// Update kernel: partial[m,k] = sum_{b in slice} sum_a x[b,m,a]*wv[b,k,a] / 256
// grid (16 m-tiles, 8 b-slices of 32), block 320 = 16 m-quads x 20 classes.
// ---------------------------------------------------------------------------
#define U_MT      64
#define U_BCH     8
#define U_THREADS 320

__global__ void __launch_bounds__(U_THREADS)
update_kernel(const float* __restrict__ x)
{
    __shared__ float xs[U_BCH][U_MT * AIN];   // 8 x 512 floats
    __shared__ float wvs[U_BCH][NK * AIN];    // 8 x 160 floats

    const int tid   = threadIdx.x;
    const int m0    = blockIdx.x * U_MT;
    const int bbase = blockIdx.y * 32;
    const int mi4   = tid / NK;               // 0..15 -> m quad
    const int k     = tid % NK;

    float acc0 = 0.f, acc1 = 0.f, acc2 = 0.f, acc3 = 0.f;

    for (int c0 = 0; c0 < 32; c0 += U_BCH) {
        __syncthreads();
        for (int i = tid; i < U_BCH * U_MT * AIN / 4; i += U_THREADS) { // 1024 f4
            int bi = i >> 7;
            int rr = i & 127;
            ((float4*)xs[bi])[rr] =
                ((const float4*)(x + (size_t)(bbase + c0 + bi) * (MUL * AIN) + m0 * AIN))[rr];
        }
        for (int i = tid; i < U_BCH * NK * AIN / 4; i += U_THREADS) {   // 320 f4
            int bi = i / 40;
            int rr = i % 40;
            ((float4*)wvs[bi])[rr] =
                ((const float4*)(g_wv + (size_t)(bbase + c0 + bi) * (NK * AIN)))[rr];
        }
        __syncthreads();

        #pragma unroll
        for (int bi = 0; bi < U_BCH; bi++) {
            const float4* wp = (const float4*)(wvs[bi] + k * AIN);
            float4 w0 = wp[0], w1 = wp[1];
            const float4* xp = (const float4*)(xs[bi] + mi4 * 4 * AIN);
            float4 x0 = xp[0], x1 = xp[1], x2 = xp[2], x3 = xp[3];
            float4 x4 = xp[4], x5 = xp[5], x6 = xp[6], x7 = xp[7];
            acc0 += x0.x*w0.x + x0.y*w0.y + x0.z*w0.z + x0.w*w0.w
                  + x1.x*w1.x + x1.y*w1.y + x1.z*w1.z + x1.w*w1.w;
            acc1 += x2.x*w0.x + x2.y*w0.y + x2.z*w0.z + x2.w*w0.w
                  + x3.x*w1.x + x3.y*w1.y + x3.z*w1.z + x3.w*w1.w;
            acc2 += x4.x*w0.x + x4.y*w0.y + x4.z*w0.z + x4.w*w0.w
                  + x5.x*w1.x + x5.y*w1.y + x5.z*w1.z + x5.w*w1.w;
            acc3 += x6.x*w0.x + x6.y*w0.y + x6.z*w0.z + x6.w*w0.w
                  + x7.x*w1.x + x7.y*w1.y + x7.z*w1.z + x7.w*w1.w;
        }
    }

    const float scale = 1.0f / 256.0f;
    float* dst = g_bpart + (size_t)blockIdx.y * (NK * MUL) + k * MUL + m0 + mi4 * 4;
    dst[0] = acc0 * scale;
    dst[1] = acc1 * scale;
    dst[2] = acc2 * scale;
    dst[3] = acc3 * scale;
}

// ---------------------------------------------------------------------------
// Softmax kernel: combine partials into b (optionally accumulating previous b),
// then c[k][m] = softmax over m. One block per class.
// ---------------------------------------------------------------------------
__global__ void __launch_bounds__(256)
softmax_kernel(int accum)
{
    const int k = blockIdx.x;
    const int t = threadIdx.x;
    const int lane = t & 31, wp = t >> 5;
    __shared__ float red[8];
    __shared__ float bc;

    float v[4];
    #pragma unroll
    for (int i = 0; i < 4; i++) {
        int m = t + i * 256;
        float b = accum ? g_b[k * MUL + m] : 0.f;
        #pragma unroll
        for (int p = 0; p < 8; p++) b += g_bpart[p * NK * MUL + k * MUL + m];
        g_b[k * MUL + m] = b;
        v[i] = b;
    }

    float mx = fmaxf(fmaxf(v[0], v[1]), fmaxf(v[2], v[3]));
    #pragma unroll
    for (int off = 16; off; off >>= 1)
        mx = fmaxf(mx, __shfl_xor_sync(0xffffffffu, mx, off));
    if (lane == 0) red[wp] = mx;
    __syncthreads();
    if (t == 0) {
        float m = red[0];
        #pragma unroll
        for (int i = 1; i < 8; i++) m = fmaxf(m, red[i]);
        bc = m;
    }
    __syncthreads();
    mx = bc;

    float s = 0.f;
    #pragma unroll
    for (int i = 0; i < 4; i++) { v[i] = expf(v[i] - mx); s += v[i]; }
    #pragma unroll
    for (int off = 16; off; off >>= 1)
        s += __shfl_xor_sync(0xffffffffu, s, off);
    __syncthreads();           // protect red[] reuse
    if (lane == 0) red[wp] = s;
    __syncthreads();
    if (t == 0) {
        float ss = 0.f;
        #pragma unroll
        for (int i = 0; i < 8; i++) ss += red[i];
        bc = ss;
    }
    __syncthreads();
    float inv = 1.0f / bc;
    float* c = g_c + k * MUL;
    #pragma unroll
    for (int i = 0; i < 4; i++) c[t + i * 256] = v[i] * inv;
}

// ---------------------------------------------------------------------------
extern "C" void kernel_launch(void* const* d_in, const int* in_sizes, int n_in,
                              void* d_out, int out_size)
{
    const float* x = (const float*)d_in[0];   // [256, 8, 1024]
    const float* W = (const float*)d_in[1];   // [20, 16, 8]
    float* out = (float*)d_out;               // [256, 20, 16, 1]

    const int F_SMEM = (BPB * XS_PER_B + NK * NO * AIN + BPB * NK * AIN
                        + BPB * NK * NO + BPB * NO) * (int)sizeof(float);
    cudaFuncSetAttribute(fused_kernel,
                         cudaFuncAttributeMaxDynamicSharedMemorySize, F_SMEM);

    dim3 ugrid(MUL / U_MT, 8);

    // Routing iteration 0 (b=0 -> uniform coefficients)
    fused_kernel<<<B_TOT / BPB, F_THREADS, F_SMEM>>>(x, W, out, 1, 0);
    update_kernel<<<ugrid, U_THREADS>>>(x);
    softmax_kernel<<<NK, 256>>>(0);

    // Routing iteration 1
    fused_kernel<<<B_TOT / BPB, F_THREADS, F_SMEM>>>(x, W, out, 0, 0);
    update_kernel<<<ugrid, U_THREADS>>>(x);
    softmax_kernel<<<NK, 256>>>(1);

    // Routing iteration 2 (final -> write v to output)
    fused_kernel<<<B_TOT / BPB, F_THREADS, F_SMEM>>>(x, W, out, 0, 1);
}

// round 3
// speedup vs baseline: 1.1724x; 1.1724x over previous
#include <cuda_runtime.h>
#include <math.h>

// Problem constants
#define B_TOT 256
#define AIN   8
#define MUL   1024
#define NK    20
#define NO    16

// Persistent scratch (device globals; allocation-free)
__device__ __align__(16) float g_c[NK * MUL];              // routing coefficients c[k][m]
__device__ __align__(16) float g_b[NK * MUL];              // logits b[k][m]
__device__ __align__(16) float g_bpart[8 * NK * MUL];      // per-b-slice partial agreement sums
__device__ __align__(16) float g_wv[B_TOT * NK * AIN];     // wv[b][k][a] = sum_o W[k,o,a]*v[b,k,o]

#define BPB        2
#define F_THREADS  640
#define XROW       12                 // padded floats per m-row (bank-conflict-free LDS.128)
#define XS_PER_B   (MUL * XROW)       // 12288 floats

#define WARP_RED_SUM(v)                                   \
  do {                                                    \
    v += __shfl_xor_sync(0xffffffffu, v, 16);             \
    v += __shfl_xor_sync(0xffffffffu, v, 8);              \
    v += __shfl_xor_sync(0xffffffffu, v, 4);              \
    v += __shfl_xor_sync(0xffffffffu, v, 2);              \
    v += __shfl_xor_sync(0xffffffffu, v, 1);              \
  } while (0)

// ---------------------------------------------------------------------------
// Fused per-batch kernel: y = c^T x, s = W y, v = squash(s), wv = W^T v.
// 2 batches per block. x staged [m][12] (padded), c staged in SMEM.
// y-phase: 10 warps, each owns (bl, class-quad); 4 classes per thread.
// ---------------------------------------------------------------------------
__global__ void __launch_bounds__(F_THREADS)
fused_kernel(const float* __restrict__ x, const float* __restrict__ W,
             float* __restrict__ out, int uniform_c, int final_iter)
{
    extern __shared__ float sm[];
    float* xs  = sm;                          // [BPB][MUL][XROW]      24576
    float* cs  = xs  + BPB * XS_PER_B;        // [NK][MUL]             20480
    float* wsm = cs  + NK * MUL;              // [NK*NO*AIN]            2560
    float* ysm = wsm + NK * NO * AIN;         // [BPB][NK][AIN]          320
    float* ssm = ysm + BPB * NK * AIN;        // [BPB][NK][NO]           640
    float* csm = ssm + BPB * NK * NO;         // [BPB][NO]                32

    const int tid = threadIdx.x;
    const int b0  = blockIdx.x * BPB;

    // ---- stage x (vectorized, padded rows) ----
    {
        const float4* xsrc = (const float4*)(x + (size_t)b0 * (MUL * AIN));
        for (int i = tid; i < BPB * MUL * 2; i += F_THREADS) {   // 4096 float4
            int bl = i >> 11;
            int r  = i & 2047;             // f4 index within batch; m = r>>1
            float4 v = xsrc[i];
            *(float4*)(xs + bl * XS_PER_B + (r >> 1) * XROW + (r & 1) * 4) = v;
        }
    }
    if (!uniform_c) {
        const float4* csrc = (const float4*)g_c;
        float4* cdst = (float4*)cs;
        for (int i = tid; i < NK * MUL / 4; i += F_THREADS) cdst[i] = csrc[i];
    }
    for (int i = tid; i < NK * NO * AIN; i += F_THREADS) wsm[i] = W[i];
    __syncthreads();

    // ---- y phase: warps 0..9; warp = (bl, quad); 4 classes/thread ----
    if (tid < 320) {
        const int w    = tid >> 5, lane = tid & 31;
        const int bl   = w / 5;
        const int k0   = (w % 5) * 4;
        const float* xb = xs + bl * XS_PER_B;

        if (uniform_c) {
            float a8[8] = {0.f, 0.f, 0.f, 0.f, 0.f, 0.f, 0.f, 0.f};
            #pragma unroll 4
            for (int j = 0; j < 32; j++) {
                const float* xr = xb + (j * 32 + lane) * XROW;
                float4 x0 = *(const float4*)xr;
                float4 x1 = *(const float4*)(xr + 4);
                a8[0] += x0.x; a8[1] += x0.y; a8[2] += x0.z; a8[3] += x0.w;
                a8[4] += x1.x; a8[5] += x1.y; a8[6] += x1.z; a8[7] += x1.w;
            }
            #pragma unroll
            for (int a = 0; a < 8; a++) { float v = a8[a]; WARP_RED_SUM(v); a8[a] = v; }
            if (lane == 0) {
                #pragma unroll
                for (int kk = 0; kk < 4; kk++) {
                    float* yb = ysm + (bl * NK + k0 + kk) * AIN;
                    #pragma unroll
                    for (int a = 0; a < 8; a++) yb[a] = a8[a] * (1.0f / 1024.0f);
                }
            }
        } else {
            float acc[32];
            #pragma unroll
            for (int i = 0; i < 32; i++) acc[i] = 0.f;
            const float* c0 = cs + (k0 + 0) * MUL;
            const float* c1 = cs + (k0 + 1) * MUL;
            const float* c2 = cs + (k0 + 2) * MUL;
            const float* c3 = cs + (k0 + 3) * MUL;
            #pragma unroll 4
            for (int j = 0; j < 32; j++) {
                const int m = j * 32 + lane;
                const float* xr = xb + m * XROW;
                float4 x0 = *(const float4*)xr;
                float4 x1 = *(const float4*)(xr + 4);
                float cv0 = c0[m], cv1 = c1[m], cv2 = c2[m], cv3 = c3[m];
                acc[0]  += cv0 * x0.x; acc[1]  += cv0 * x0.y;
                acc[2]  += cv0 * x0.z; acc[3]  += cv0 * x0.w;
                acc[4]  += cv0 * x1.x; acc[5]  += cv0 * x1.y;
                acc[6]  += cv0 * x1.z; acc[7]  += cv0 * x1.w;
                acc[8]  += cv1 * x0.x; acc[9]  += cv1 * x0.y;
                acc[10] += cv1 * x0.z; acc[11] += cv1 * x0.w;
                acc[12] += cv1 * x1.x; acc[13] += cv1 * x1.y;
                acc[14] += cv1 * x1.z; acc[15] += cv1 * x1.w;
                acc[16] += cv2 * x0.x; acc[17] += cv2 * x0.y;
                acc[18] += cv2 * x0.z; acc[19] += cv2 * x0.w;
                acc[20] += cv2 * x1.x; acc[21] += cv2 * x1.y;
                acc[22] += cv2 * x1.z; acc[23] += cv2 * x1.w;
                acc[24] += cv3 * x0.x; acc[25] += cv3 * x0.y;
                acc[26] += cv3 * x0.z; acc[27] += cv3 * x0.w;
                acc[28] += cv3 * x1.x; acc[29] += cv3 * x1.y;
                acc[30] += cv3 * x1.z; acc[31] += cv3 * x1.w;
            }
            #pragma unroll
            for (int i = 0; i < 32; i++) { float v = acc[i]; WARP_RED_SUM(v); acc[i] = v; }
            if (lane == 0) {
                #pragma unroll
                for (int kk = 0; kk < 4; kk++) {
                    float* yb = ysm + (bl * NK + k0 + kk) * AIN;
                    #pragma unroll
                    for (int a = 0; a < 8; a++) yb[a] = acc[kk * 8 + a];
                }
            }
        }
    }
    __syncthreads();

    // ---- s phase: tid -> (bl, k, o) ----
    const int bl = tid / (NK * NO);
    const int r  = tid % (NK * NO);
    const int k  = r / NO;
    const int o  = r % NO;
    {
        const float* wk = wsm + (k * NO + o) * AIN;
        const float* yk = ysm + (bl * NK + k) * AIN;
        float s = 0.f;
        #pragma unroll
        for (int a = 0; a < AIN; a++) s += wk[a] * yk[a];
        ssm[tid] = s;
        __syncthreads();

        // squash coefficient: sum over classes (axis=1 in the reference)
        if (tid < BPB * NO) {
            int bb = tid / NO, oo = tid % NO;
            float msq = 0.f;
            #pragma unroll
            for (int kk = 0; kk < NK; kk++) {
                float t = ssm[bb * NK * NO + kk * NO + oo];
                msq += t * t;
            }
            csm[tid] = msq / ((1.f + msq) * sqrtf(msq));
        }
        __syncthreads();

        float v = csm[bl * NO + o] * s;
        if (final_iter) {
            out[(size_t)(b0 + bl) * (NK * NO) + r] = v;   // perfectly coalesced
        }
        ssm[tid] = v;
    }
    __syncthreads();

    // ---- wv phase (skipped on final iteration) ----
    if (!final_iter && tid < BPB * NK * AIN) {
        int bb = tid / (NK * AIN);
        int rr = tid % (NK * AIN);
        int kk = rr / AIN, aa = rr % AIN;
        float acc = 0.f;
        #pragma unroll
        for (int oo = 0; oo < NO; oo++)
            acc += wsm[(kk * NO + oo) * AIN + aa] * ssm[bb * NK * NO + kk * NO + oo];
        g_wv[(size_t)(b0 + bb) * (NK * AIN) + rr] = acc;
    }
}

// ---------------------------------------------------------------------------
// Update kernel: partial[m,k] = sum_{b in slice} sum_a x[b,m,a]*wv[b,k,a] / 256
// ---------------------------------------------------------------------------
#define U_MT      64
#define U_BCH     8
#define U_THREADS 320

__global__ void __launch_bounds__(U_THREADS)
update_kernel(const float* __restrict__ x)
{
    __shared__ float xs[U_BCH][U_MT * AIN];
    __shared__ float wvs[U_BCH][NK * AIN];

    const int tid   = threadIdx.x;
    const int m0    = blockIdx.x * U_MT;
    const int bbase = blockIdx.y * 32;
    const int mi4   = tid / NK;
    const int k     = tid % NK;

    float acc0 = 0.f, acc1 = 0.f, acc2 = 0.f, acc3 = 0.f;

    for (int c0 = 0; c0 < 32; c0 += U_BCH) {
        __syncthreads();
        for (int i = tid; i < U_BCH * U_MT * AIN / 4; i += U_THREADS) {
            int bi = i >> 7;
            int rr = i & 127;
            ((float4*)xs[bi])[rr] =
                ((const float4*)(x + (size_t)(bbase + c0 + bi) * (MUL * AIN) + m0 * AIN))[rr];
        }
        for (int i = tid; i < U_BCH * NK * AIN / 4; i += U_THREADS) {
            int bi = i / 40;
            int rr = i % 40;
            ((float4*)wvs[bi])[rr] =
                ((const float4*)(g_wv + (size_t)(bbase + c0 + bi) * (NK * AIN)))[rr];
        }
        __syncthreads();

        #pragma unroll
        for (int bi = 0; bi < U_BCH; bi++) {
            const float4* wp = (const float4*)(wvs[bi] + k * AIN);
            float4 w0 = wp[0], w1 = wp[1];
            const float4* xp = (const float4*)(xs[bi] + mi4 * 4 * AIN);
            float4 x0 = xp[0], x1 = xp[1], x2 = xp[2], x3 = xp[3];
            float4 x4 = xp[4], x5 = xp[5], x6 = xp[6], x7 = xp[7];
            acc0 += x0.x*w0.x + x0.y*w0.y + x0.z*w0.z + x0.w*w0.w
                  + x1.x*w1.x + x1.y*w1.y + x1.z*w1.z + x1.w*w1.w;
            acc1 += x2.x*w0.x + x2.y*w0.y + x2.z*w0.z + x2.w*w0.w
                  + x3.x*w1.x + x3.y*w1.y + x3.z*w1.z + x3.w*w1.w;
            acc2 += x4.x*w0.x + x4.y*w0.y + x4.z*w0.z + x4.w*w0.w
                  + x5.x*w1.x + x5.y*w1.y + x5.z*w1.z + x5.w*w1.w;
            acc3 += x6.x*w0.x + x6.y*w0.y + x6.z*w0.z + x6.w*w0.w
                  + x7.x*w1.x + x7.y*w1.y + x7.z*w1.z + x7.w*w1.w;
        }
    }

    const float scale = 1.0f / 256.0f;
    float* dst = g_bpart + (size_t)blockIdx.y * (NK * MUL) + k * MUL + m0 + mi4 * 4;
    dst[0] = acc0 * scale;
    dst[1] = acc1 * scale;
    dst[2] = acc2 * scale;
    dst[3] = acc3 * scale;
}

// ---------------------------------------------------------------------------
// Softmax kernel: combine partials into b (optionally accumulating), softmax over m.
// ---------------------------------------------------------------------------
__global__ void __launch_bounds__(256)
softmax_kernel(int accum)
{
    const int k = blockIdx.x;
    const int t = threadIdx.x;
    const int lane = t & 31, wp = t >> 5;
    __shared__ float red[8];
    __shared__ float bc;

    float v[4];
    #pragma unroll
    for (int i = 0; i < 4; i++) {
        int m = t + i * 256;
        float b = accum ? g_b[k * MUL + m] : 0.f;
        #pragma unroll
        for (int p = 0; p < 8; p++) b += g_bpart[p * NK * MUL + k * MUL + m];
        g_b[k * MUL + m] = b;
        v[i] = b;
    }

    float mx = fmaxf(fmaxf(v[0], v[1]), fmaxf(v[2], v[3]));
    #pragma unroll
    for (int off = 16; off; off >>= 1)
        mx = fmaxf(mx, __shfl_xor_sync(0xffffffffu, mx, off));
    if (lane == 0) red[wp] = mx;
    __syncthreads();
    if (t == 0) {
        float m = red[0];
        #pragma unroll
        for (int i = 1; i < 8; i++) m = fmaxf(m, red[i]);
        bc = m;
    }
    __syncthreads();
    mx = bc;

    float s = 0.f;
    #pragma unroll
    for (int i = 0; i < 4; i++) { v[i] = expf(v[i] - mx); s += v[i]; }
    #pragma unroll
    for (int off = 16; off; off >>= 1)
        s += __shfl_xor_sync(0xffffffffu, s, off);
    __syncthreads();
    if (lane == 0) red[wp] = s;
    __syncthreads();
    if (t == 0) {
        float ss = 0.f;
        #pragma unroll
        for (int i = 0; i < 8; i++) ss += red[i];
        bc = ss;
    }
    __syncthreads();
    float inv = 1.0f / bc;
    float* c = g_c + k * MUL;
    #pragma unroll
    for (int i = 0; i < 4; i++) c[t + i * 256] = v[i] * inv;
}

// ---------------------------------------------------------------------------
extern "C" void kernel_launch(void* const* d_in, const int* in_sizes, int n_in,
                              void* d_out, int out_size)
{
    const float* x = (const float*)d_in[0];   // [256, 8, 1024] (viewed as [256][1024][8])
    const float* W = (const float*)d_in[1];   // [20, 16, 8]
    float* out = (float*)d_out;               // [256, 20, 16, 1]

    const int F_SMEM = (BPB * XS_PER_B + NK * MUL + NK * NO * AIN
                        + BPB * NK * AIN + BPB * NK * NO + BPB * NO)
                       * (int)sizeof(float);
    cudaFuncSetAttribute(fused_kernel,
                         cudaFuncAttributeMaxDynamicSharedMemorySize, F_SMEM);

    dim3 ugrid(MUL / U_MT, 8);

    // Routing iteration 0 (b=0 -> uniform coefficients)
    fused_kernel<<<B_TOT / BPB, F_THREADS, F_SMEM>>>(x, W, out, 1, 0);
    update_kernel<<<ugrid, U_THREADS>>>(x);
    softmax_kernel<<<NK, 256>>>(0);

    // Routing iteration 1
    fused_kernel<<<B_TOT / BPB, F_THREADS, F_SMEM>>>(x, W, out, 0, 0);
    update_kernel<<<ugrid, U_THREADS>>>(x);
    softmax_kernel<<<NK, 256>>>(1);

    // Routing iteration 2 (final -> write v to output)
    fused_kernel<<<B_TOT / BPB, F_THREADS, F_SMEM>>>(x, W, out, 0, 1);
}

// round 4
// speedup vs baseline: 1.2122x; 1.0339x over previous
#include <cuda_runtime.h>
#include <math.h>

// Problem constants
#define B_TOT 256
#define AIN   8
#define MUL   1024
#define NK    20
#define NO    16

// Persistent scratch (device globals; allocation-free)
__device__ __align__(16) float g_c[NK * MUL];
__device__ __align__(16) float g_b[NK * MUL];
__device__ __align__(16) float g_bpart[8 * NK * MUL];
__device__ __align__(16) float g_wv[B_TOT * NK * AIN];

// Packed f32x2 helpers (Blackwell FFMA2 path)
#define FMA2(acc, a, b) \
    asm("fma.rn.f32x2 %0, %1, %2, %0;" : "+l"(acc) : "l"(a), "l"(b))
#define ADD2(acc, a) \
    asm("add.rn.f32x2 %0, %1, %0;" : "+l"(acc) : "l"(a))

__device__ __forceinline__ float pair_sum(unsigned long long u) {
    float lo = __uint_as_float((unsigned)(u & 0xffffffffu));
    float hi = __uint_as_float((unsigned)(u >> 32));
    return lo + hi;
}

#define BPB        2
#define F_THREADS  640
#define PL         1040                // plane stride (floats), 16B-aligned, conflict-free
#define XSB        (AIN * PL)          // 8320 floats per batch

#define WARP_RED_SUM(v)                                   \
  do {                                                    \
    v += __shfl_xor_sync(0xffffffffu, v, 16);             \
    v += __shfl_xor_sync(0xffffffffu, v, 8);              \
    v += __shfl_xor_sync(0xffffffffu, v, 4);              \
    v += __shfl_xor_sync(0xffffffffu, v, 2);              \
    v += __shfl_xor_sync(0xffffffffu, v, 1);              \
  } while (0)

// ---------------------------------------------------------------------------
// Fused kernel: y = c^T x (f32x2 over m-pairs), s = W y, v = squash, wv = W^T v.
// 2 batches/block; x staged plane-major [bl][a][m]; 20 y-warps = (bl,kquad,mhalf).
// ---------------------------------------------------------------------------
__global__ void __launch_bounds__(F_THREADS)
fused_kernel(const float* __restrict__ x, const float* __restrict__ W,
             float* __restrict__ out, int uniform_c, int final_iter)
{
    extern __shared__ float sm[];
    float* xs  = sm;                          // [BPB][AIN][PL]   16640
    float* cs  = xs  + BPB * XSB;             // [NK][MUL]        20480
    float* wsm = cs  + NK * MUL;              // 2560
    float* ysm = wsm + NK * NO * AIN;         // [2 mh][BPB][NK][AIN] 640
    float* ssm = ysm + 2 * BPB * NK * AIN;    // [BPB][NK][NO]    640
    float* csm = ssm + BPB * NK * NO;         // [BPB][NO]        32

    const int tid = threadIdx.x;
    const int b0  = blockIdx.x * BPB;

    // ---- stage x transposed to planes: xs[bl][a][m] ----
    {
        const float4* xsrc = (const float4*)(x + (size_t)b0 * (MUL * AIN));
        for (int i = tid; i < BPB * MUL; i += F_THREADS) {   // 2048 m-rows
            int bl = i >> 10;
            int m  = i & 1023;
            float4 v0 = xsrc[i * 2];
            float4 v1 = xsrc[i * 2 + 1];
            float* base = xs + bl * XSB + m;
            base[0 * PL] = v0.x; base[1 * PL] = v0.y;
            base[2 * PL] = v0.z; base[3 * PL] = v0.w;
            base[4 * PL] = v1.x; base[5 * PL] = v1.y;
            base[6 * PL] = v1.z; base[7 * PL] = v1.w;
        }
    }
    if (!uniform_c) {
        const float4* csrc = (const float4*)g_c;
        float4* cdst = (float4*)cs;
        for (int i = tid; i < NK * MUL / 4; i += F_THREADS) cdst[i] = csrc[i];
    }
    {
        const float4* wsrc = (const float4*)W;
        float4* wdst = (float4*)wsm;
        for (int i = tid; i < NK * NO * AIN / 4; i += F_THREADS) wdst[i] = wsrc[i];
    }
    __syncthreads();

    // ---- y phase: 20 warps = (bl, kquad, mhalf); 4 classes/thread, f32x2 ----
    {
        const int w = tid >> 5, lane = tid & 31;
        const int bl = w / 10;
        const int r2 = w % 10;
        const int kq = r2 >> 1;
        const int mh = r2 & 1;
        const int k0 = kq * 4;
        const float* xb = xs + bl * XSB;
        const int mbase = mh * 512;

        if (uniform_c) {
            // y = mean over m (c uniform = 1/1024); only kq==0 warps compute
            if (kq == 0) {
                unsigned long long a8[8];
                #pragma unroll
                for (int a = 0; a < 8; a++) a8[a] = 0ull;
                #pragma unroll
                for (int j = 0; j < 4; j++) {
                    const int m = mbase + j * 128 + lane * 4;
                    #pragma unroll
                    for (int a = 0; a < 8; a++) {
                        ulonglong2 xv = *(const ulonglong2*)(xb + a * PL + m);
                        ADD2(a8[a], xv.x);
                        ADD2(a8[a], xv.y);
                    }
                }
                #pragma unroll
                for (int a = 0; a < 8; a++) {
                    float v = pair_sum(a8[a]);
                    WARP_RED_SUM(v);
                    if (lane == 0) {
                        float yv = v * (1.0f / 1024.0f);
                        #pragma unroll
                        for (int kk = 0; kk < NK; kk++)
                            ysm[((mh * BPB + bl) * NK + kk) * AIN + a] = yv;
                    }
                }
            }
        } else {
            unsigned long long acc[4][8];
            #pragma unroll
            for (int kk = 0; kk < 4; kk++)
                #pragma unroll
                for (int a = 0; a < 8; a++) acc[kk][a] = 0ull;

            #pragma unroll
            for (int j = 0; j < 4; j++) {
                const int m = mbase + j * 128 + lane * 4;
                ulonglong2 cP0 = *(const ulonglong2*)(cs + (k0 + 0) * MUL + m);
                ulonglong2 cP1 = *(const ulonglong2*)(cs + (k0 + 1) * MUL + m);
                ulonglong2 cP2 = *(const ulonglong2*)(cs + (k0 + 2) * MUL + m);
                ulonglong2 cP3 = *(const ulonglong2*)(cs + (k0 + 3) * MUL + m);
                #pragma unroll
                for (int a = 0; a < 8; a++) {
                    ulonglong2 xv = *(const ulonglong2*)(xb + a * PL + m);
                    FMA2(acc[0][a], cP0.x, xv.x); FMA2(acc[0][a], cP0.y, xv.y);
                    FMA2(acc[1][a], cP1.x, xv.x); FMA2(acc[1][a], cP1.y, xv.y);
                    FMA2(acc[2][a], cP2.x, xv.x); FMA2(acc[2][a], cP2.y, xv.y);
                    FMA2(acc[3][a], cP3.x, xv.x); FMA2(acc[3][a], cP3.y, xv.y);
                }
            }
            #pragma unroll
            for (int kk = 0; kk < 4; kk++) {
                #pragma unroll
                for (int a = 0; a < 8; a++) {
                    float v = pair_sum(acc[kk][a]);
                    WARP_RED_SUM(v);
                    if (lane == 0)
                        ysm[((mh * BPB + bl) * NK + (k0 + kk)) * AIN + a] = v;
                }
            }
        }
    }
    __syncthreads();

    // ---- s phase: tid -> (bl, k, o); combine the two m-halves ----
    const int bl = tid / (NK * NO);
    const int r  = tid % (NK * NO);
    const int k  = r / NO;
    const int o  = r % NO;
    {
        const float* wk  = wsm + (k * NO + o) * AIN;
        const float* yk0 = ysm + ((0 * BPB + bl) * NK + k) * AIN;
        const float* yk1 = ysm + ((1 * BPB + bl) * NK + k) * AIN;
        float s = 0.f;
        #pragma unroll
        for (int a = 0; a < AIN; a++) s += wk[a] * (yk0[a] + yk1[a]);
        ssm[tid] = s;
        __syncthreads();

        // squash coefficient: reduction over classes (axis=1 in the reference)
        if (tid < BPB * NO) {
            int bb = tid / NO, oo = tid % NO;
            float msq = 0.f;
            #pragma unroll
            for (int kk = 0; kk < NK; kk++) {
                float t = ssm[bb * NK * NO + kk * NO + oo];
                msq += t * t;
            }
            csm[tid] = msq / ((1.f + msq) * sqrtf(msq));
        }
        __syncthreads();

        float v = csm[bl * NO + o] * s;
        if (final_iter) {
            out[(size_t)(b0 + bl) * (NK * NO) + r] = v;   // coalesced
        }
        ssm[tid] = v;
    }
    __syncthreads();

    // ---- wv phase (skipped on final iteration) ----
    if (!final_iter && tid < BPB * NK * AIN) {
        int bb = tid / (NK * AIN);
        int rr = tid % (NK * AIN);
        int kk = rr / AIN, aa = rr % AIN;
        float acc = 0.f;
        #pragma unroll
        for (int oo = 0; oo < NO; oo++)
            acc += wsm[(kk * NO + oo) * AIN + aa] * ssm[bb * NK * NO + kk * NO + oo];
        g_wv[(size_t)(b0 + bb) * (NK * AIN) + rr] = acc;
    }
}

// ---------------------------------------------------------------------------
// Update kernel: partial[m,k] = sum_{b in slice} sum_a x[b,m,a]*wv[b,k,a] / 256
// f32x2 over a-pairs.
// ---------------------------------------------------------------------------
#define U_MT      64
#define U_BCH     8
#define U_THREADS 320

__global__ void __launch_bounds__(U_THREADS)
update_kernel(const float* __restrict__ x)
{
    __shared__ float xs[U_BCH][U_MT * AIN];
    __shared__ float wvs[U_BCH][NK * AIN];

    const int tid   = threadIdx.x;
    const int m0    = blockIdx.x * U_MT;
    const int bbase = blockIdx.y * 32;
    const int mi4   = tid / NK;
    const int k     = tid % NK;

    unsigned long long acc[4];
    #pragma unroll
    for (int i = 0; i < 4; i++) acc[i] = 0ull;

    for (int c0 = 0; c0 < 32; c0 += U_BCH) {
        __syncthreads();
        for (int i = tid; i < U_BCH * U_MT * AIN / 4; i += U_THREADS) {
            int bi = i >> 7;
            int rr = i & 127;
            ((float4*)xs[bi])[rr] =
                ((const float4*)(x + (size_t)(bbase + c0 + bi) * (MUL * AIN) + m0 * AIN))[rr];
        }
        for (int i = tid; i < U_BCH * NK * AIN / 4; i += U_THREADS) {
            int bi = i / 40;
            int rr = i % 40;
            ((float4*)wvs[bi])[rr] =
                ((const float4*)(g_wv + (size_t)(bbase + c0 + bi) * (NK * AIN)))[rr];
        }
        __syncthreads();

        #pragma unroll
        for (int bi = 0; bi < U_BCH; bi++) {
            const ulonglong2* wp = (const ulonglong2*)(wvs[bi] + k * AIN);
            ulonglong2 wA = wp[0], wB = wp[1];
            const ulonglong2* xp = (const ulonglong2*)(xs[bi] + mi4 * 4 * AIN);
            #pragma unroll
            for (int mm = 0; mm < 4; mm++) {
                ulonglong2 xA = xp[mm * 2];
                ulonglong2 xB = xp[mm * 2 + 1];
                FMA2(acc[mm], xA.x, wA.x);
                FMA2(acc[mm], xA.y, wA.y);
                FMA2(acc[mm], xB.x, wB.x);
                FMA2(acc[mm], xB.y, wB.y);
            }
        }
    }

    const float scale = 1.0f / 256.0f;
    float* dst = g_bpart + (size_t)blockIdx.y * (NK * MUL) + k * MUL + m0 + mi4 * 4;
    #pragma unroll
    for (int mm = 0; mm < 4; mm++) dst[mm] = pair_sum(acc[mm]) * scale;
}

// ---------------------------------------------------------------------------
// Softmax kernel: combine partials into b (optionally accumulating), softmax over m.
// ---------------------------------------------------------------------------
__global__ void __launch_bounds__(256)
softmax_kernel(int accum)
{
    const int k = blockIdx.x;
    const int t = threadIdx.x;
    const int lane = t & 31, wp = t >> 5;
    __shared__ float red[8];
    __shared__ float bc;

    float v[4];
    #pragma unroll
    for (int i = 0; i < 4; i++) {
        int m = t + i * 256;
        float b = accum ? g_b[k * MUL + m] : 0.f;
        #pragma unroll
        for (int p = 0; p < 8; p++) b += g_bpart[p * NK * MUL + k * MUL + m];
        g_b[k * MUL + m] = b;
        v[i] = b;
    }

    float mx = fmaxf(fmaxf(v[0], v[1]), fmaxf(v[2], v[3]));
    #pragma unroll
    for (int off = 16; off; off >>= 1)
        mx = fmaxf(mx, __shfl_xor_sync(0xffffffffu, mx, off));
    if (lane == 0) red[wp] = mx;
    __syncthreads();
    if (t == 0) {
        float m = red[0];
        #pragma unroll
        for (int i = 1; i < 8; i++) m = fmaxf(m, red[i]);
        bc = m;
    }
    __syncthreads();
    mx = bc;

    float s = 0.f;
    #pragma unroll
    for (int i = 0; i < 4; i++) { v[i] = expf(v[i] - mx); s += v[i]; }
    #pragma unroll
    for (int off = 16; off; off >>= 1)
        s += __shfl_xor_sync(0xffffffffu, s, off);
    __syncthreads();
    if (lane == 0) red[wp] = s;
    __syncthreads();
    if (t == 0) {
        float ss = 0.f;
        #pragma unroll
        for (int i = 0; i < 8; i++) ss += red[i];
        bc = ss;
    }
    __syncthreads();
    float inv = 1.0f / bc;
    float* c = g_c + k * MUL;
    #pragma unroll
    for (int i = 0; i < 4; i++) c[t + i * 256] = v[i] * inv;
}

// ---------------------------------------------------------------------------
extern "C" void kernel_launch(void* const* d_in, const int* in_sizes, int n_in,
                              void* d_out, int out_size)
{
    const float* x = (const float*)d_in[0];   // [256][1024][8] flat
    const float* W = (const float*)d_in[1];   // [20][16][8]
    float* out = (float*)d_out;               // [256][20][16][1]

    const int F_SMEM = (BPB * XSB + NK * MUL + NK * NO * AIN
                        + 2 * BPB * NK * AIN + BPB * NK * NO + BPB * NO)
                       * (int)sizeof(float);
    cudaFuncSetAttribute(fused_kernel,
                         cudaFuncAttributeMaxDynamicSharedMemorySize, F_SMEM);

    dim3 ugrid(MUL / U_MT, 8);

    // iter 0 (b=0 -> uniform coefficients)
    fused_kernel<<<B_TOT / BPB, F_THREADS, F_SMEM>>>(x, W, out, 1, 0);
    update_kernel<<<ugrid, U_THREADS>>>(x);
    softmax_kernel<<<NK, 256>>>(0);

    // iter 1
    fused_kernel<<<B_TOT / BPB, F_THREADS, F_SMEM>>>(x, W, out, 0, 0);
    update_kernel<<<ugrid, U_THREADS>>>(x);
    softmax_kernel<<<NK, 256>>>(1);

    // iter 2 (final -> write v)
    fused_kernel<<<B_TOT / BPB, F_THREADS, F_SMEM>>>(x, W, out, 0, 1);
}

// round 5
// speedup vs baseline: 1.2128x; 1.0005x over previous
#include <cuda_runtime.h>
#include <math.h>

// Problem constants
#define B_TOT 256
#define AIN   8
#define MUL   1024
#define NK    20
#define NO    16

// Persistent scratch (device globals; allocation-free)
__device__ __align__(16) float g_c[NK * MUL];
__device__ __align__(16) float g_b[NK * MUL];
__device__ __align__(16) float g_bpart[8 * NK * MUL];
__device__ __align__(16) float g_wv[B_TOT * NK * AIN];
__device__ __align__(16) float g_xt[B_TOT * MUL * AIN];   // x transposed: [b][a][m]

// Packed f32x2 helpers
#define FMA2(acc, a, b) \
    asm("fma.rn.f32x2 %0, %1, %2, %0;" : "+l"(acc) : "l"(a), "l"(b))

__device__ __forceinline__ float pair_sum(unsigned long long u) {
    float lo = __uint_as_float((unsigned)(u & 0xffffffffu));
    float hi = __uint_as_float((unsigned)(u >> 32));
    return lo + hi;
}

#define WARP_RED_SUM(v)                                   \
  do {                                                    \
    v += __shfl_xor_sync(0xffffffffu, v, 16);             \
    v += __shfl_xor_sync(0xffffffffu, v, 8);              \
    v += __shfl_xor_sync(0xffffffffu, v, 4);              \
    v += __shfl_xor_sync(0xffffffffu, v, 2);              \
    v += __shfl_xor_sync(0xffffffffu, v, 1);              \
  } while (0)

#define PL 1040                       // plane stride (floats), conflict-free

// ---------------------------------------------------------------------------
// Prep kernel: one block per batch. Transposes x[b] (flat [m][a]) into
// g_xt[b][a][m], and performs the ENTIRE iteration-0 fused step (uniform c):
// y0 = mean_m x, s0 = W y0, v0 = squash(s0), wv0 = W^T v0 -> g_wv.
// ---------------------------------------------------------------------------
#define P_THREADS 320

__global__ void __launch_bounds__(P_THREADS)
prep_kernel(const float* __restrict__ x, const float* __restrict__ W)
{
    __shared__ float xsm[MUL * 9];            // padded rows [m][9]
    __shared__ float wsm[NK * NO * AIN];
    __shared__ float y0[AIN];
    __shared__ float ssm[NK * NO];
    __shared__ float csm[NO];

    const int tid = threadIdx.x;
    const int b   = blockIdx.x;

    // stage x[b] rows (flat [m][a]) into padded SMEM
    const float4* xsrc = (const float4*)(x + (size_t)b * (MUL * AIN));
    for (int i = tid; i < MUL * 2; i += P_THREADS) {
        float4 v = xsrc[i];
        int m = i >> 1, h = i & 1;
        float* d = xsm + m * 9 + h * 4;
        d[0] = v.x; d[1] = v.y; d[2] = v.z; d[3] = v.w;
    }
    for (int i = tid; i < NK * NO * AIN / 4; i += P_THREADS)
        ((float4*)wsm)[i] = ((const float4*)W)[i];
    __syncthreads();

    // write transposed planes xt[b][a][m], coalesced float4
    float4* xdst = (float4*)(g_xt + (size_t)b * (MUL * AIN));
    for (int i = tid; i < MUL * 2; i += P_THREADS) {
        int a  = i >> 8;              // 2048 f4 = 8 planes x 256 f4
        int q  = i & 255;
        int m4 = q * 4;
        float4 v;
        v.x = xsm[(m4 + 0) * 9 + a];
        v.y = xsm[(m4 + 1) * 9 + a];
        v.z = xsm[(m4 + 2) * 9 + a];
        v.w = xsm[(m4 + 3) * 9 + a];
        xdst[a * 256 + q] = v;
    }

    // xsum per atom -> y0 (iteration-0 y with uniform c = 1/1024)
    {
        int w = tid >> 5, lane = tid & 31;
        if (w < 8) {
            float s = 0.f;
            #pragma unroll 8
            for (int t = 0; t < 32; t++) s += xsm[(t * 32 + lane) * 9 + w];
            WARP_RED_SUM(s);
            if (lane == 0) y0[w] = s * (1.0f / 1024.0f);
        }
    }
    __syncthreads();

    // s0 / squash / v0 / wv0
    const int k = tid >> 4, o = tid & 15;
    const float* wk = wsm + (k * NO + o) * AIN;
    float s = 0.f;
    #pragma unroll
    for (int a = 0; a < AIN; a++) s += wk[a] * y0[a];
    ssm[tid] = s;
    __syncthreads();

    if (tid < NO) {
        float msq = 0.f;
        #pragma unroll
        for (int kk = 0; kk < NK; kk++) {
            float t = ssm[kk * NO + tid];
            msq += t * t;
        }
        csm[tid] = msq / ((1.f + msq) * sqrtf(msq));
    }
    __syncthreads();

    float v = csm[o] * s;
    ssm[tid] = v;
    __syncthreads();

    if (tid < NK * AIN) {
        int kk = tid >> 3, aa = tid & 7;
        float acc = 0.f;
        #pragma unroll
        for (int oo = 0; oo < NO; oo++)
            acc += wsm[(kk * NO + oo) * AIN + aa] * ssm[kk * NO + oo];
        g_wv[(size_t)b * (NK * AIN) + tid] = acc;
    }
}

// ---------------------------------------------------------------------------
// Fused kernel (iterations 1,2): one block per batch, 320 threads (10 warps).
// y = c^T x (c streamed from global/L2, x from SMEM planes), s = W y,
// v = squash(s), wv = W^T v (or write out on final iteration).
// ---------------------------------------------------------------------------
#define F_THREADS 320

__global__ void __launch_bounds__(F_THREADS, 2)
fused_kernel(const float* __restrict__ W, float* __restrict__ out, int final_iter)
{
    __shared__ float xs[AIN * PL];            // planes [a][m]  33280 B
    __shared__ float wsm[NK * NO * AIN];      // 10240 B
    __shared__ float ysm[2 * NK * AIN];       // [mh][k][a]
    __shared__ float ssm[NK * NO];
    __shared__ float csm[NO];

    const int tid = threadIdx.x;
    const int b   = blockIdx.x;

    // stage x planes (straight vectorized copy from pre-transposed g_xt)
    {
        const float4* xsrc = (const float4*)(g_xt + (size_t)b * (MUL * AIN));
        for (int i = tid; i < MUL * 2; i += F_THREADS) {
            int a = i >> 8;
            int q = i & 255;
            *(float4*)(xs + a * PL + q * 4) = xsrc[i];
        }
    }
    for (int i = tid; i < NK * NO * AIN / 4; i += F_THREADS)
        ((float4*)wsm)[i] = ((const float4*)W)[i];
    __syncthreads();

    // ---- y phase: 10 warps = (kquad, mhalf); 4 classes/thread, f32x2 ----
    {
        const int w = tid >> 5, lane = tid & 31;
        const int kq = w >> 1;
        const int mh = w & 1;
        const int k0 = kq * 4;
        const int mbase = mh * 512;

        unsigned long long acc[4][8];
        #pragma unroll
        for (int kk = 0; kk < 4; kk++)
            #pragma unroll
            for (int a = 0; a < 8; a++) acc[kk][a] = 0ull;

        #pragma unroll
        for (int j = 0; j < 4; j++) {
            const int m = mbase + j * 128 + lane * 4;
            ulonglong2 cP0 = *(const ulonglong2*)(g_c + (k0 + 0) * MUL + m);
            ulonglong2 cP1 = *(const ulonglong2*)(g_c + (k0 + 1) * MUL + m);
            ulonglong2 cP2 = *(const ulonglong2*)(g_c + (k0 + 2) * MUL + m);
            ulonglong2 cP3 = *(const ulonglong2*)(g_c + (k0 + 3) * MUL + m);
            #pragma unroll
            for (int a = 0; a < 8; a++) {
                ulonglong2 xv = *(const ulonglong2*)(xs + a * PL + m);
                FMA2(acc[0][a], cP0.x, xv.x); FMA2(acc[0][a], cP0.y, xv.y);
                FMA2(acc[1][a], cP1.x, xv.x); FMA2(acc[1][a], cP1.y, xv.y);
                FMA2(acc[2][a], cP2.x, xv.x); FMA2(acc[2][a], cP2.y, xv.y);
                FMA2(acc[3][a], cP3.x, xv.x); FMA2(acc[3][a], cP3.y, xv.y);
            }
        }
        #pragma unroll
        for (int kk = 0; kk < 4; kk++) {
            #pragma unroll
            for (int a = 0; a < 8; a++) {
                float v = pair_sum(acc[kk][a]);
                WARP_RED_SUM(v);
                if (lane == 0)
                    ysm[(mh * NK + (k0 + kk)) * AIN + a] = v;
            }
        }
    }
    __syncthreads();

    // ---- s phase: tid -> (k, o); combine m-halves ----
    const int k = tid >> 4;
    const int o = tid & 15;
    {
        const float* wk  = wsm + (k * NO + o) * AIN;
        const float* yk0 = ysm + k * AIN;
        const float* yk1 = ysm + (NK + k) * AIN;
        float s = 0.f;
        #pragma unroll
        for (int a = 0; a < AIN; a++) s += wk[a] * (yk0[a] + yk1[a]);
        ssm[tid] = s;
        __syncthreads();

        if (tid < NO) {
            float msq = 0.f;
            #pragma unroll
            for (int kk = 0; kk < NK; kk++) {
                float t = ssm[kk * NO + tid];
                msq += t * t;
            }
            csm[tid] = msq / ((1.f + msq) * sqrtf(msq));
        }
        __syncthreads();

        float v = csm[o] * s;
        if (final_iter) {
            out[(size_t)b * (NK * NO) + tid] = v;   // coalesced
        }
        ssm[tid] = v;
    }
    __syncthreads();

    // ---- wv phase (skipped on final iteration) ----
    if (!final_iter && tid < NK * AIN) {
        int kk = tid >> 3, aa = tid & 7;
        float acc = 0.f;
        #pragma unroll
        for (int oo = 0; oo < NO; oo++)
            acc += wsm[(kk * NO + oo) * AIN + aa] * ssm[kk * NO + oo];
        g_wv[(size_t)b * (NK * AIN) + tid] = acc;
    }
}

// ---------------------------------------------------------------------------
// Update kernel: partial[m,k] = sum_{b in slice} sum_a x[b,m,a]*wv[b,k,a] / 256
// ---------------------------------------------------------------------------
#define U_MT      64
#define U_BCH     8
#define U_THREADS 320

__global__ void __launch_bounds__(U_THREADS)
update_kernel(const float* __restrict__ x)
{
    __shared__ float xs[U_BCH][U_MT * AIN];
    __shared__ float wvs[U_BCH][NK * AIN];

    const int tid   = threadIdx.x;
    const int m0    = blockIdx.x * U_MT;
    const int bbase = blockIdx.y * 32;
    const int mi4   = tid / NK;
    const int k     = tid % NK;

    unsigned long long acc[4];
    #pragma unroll
    for (int i = 0; i < 4; i++) acc[i] = 0ull;

    for (int c0 = 0; c0 < 32; c0 += U_BCH) {
        __syncthreads();
        for (int i = tid; i < U_BCH * U_MT * AIN / 4; i += U_THREADS) {
            int bi = i >> 7;
            int rr = i & 127;
            ((float4*)xs[bi])[rr] =
                ((const float4*)(x + (size_t)(bbase + c0 + bi) * (MUL * AIN) + m0 * AIN))[rr];
        }
        for (int i = tid; i < U_BCH * NK * AIN / 4; i += U_THREADS) {
            int bi = i / 40;
            int rr = i % 40;
            ((float4*)wvs[bi])[rr] =
                ((const float4*)(g_wv + (size_t)(bbase + c0 + bi) * (NK * AIN)))[rr];
        }
        __syncthreads();

        #pragma unroll
        for (int bi = 0; bi < U_BCH; bi++) {
            const ulonglong2* wp = (const ulonglong2*)(wvs[bi] + k * AIN);
            ulonglong2 wA = wp[0], wB = wp[1];
            const ulonglong2* xp = (const ulonglong2*)(xs[bi] + mi4 * 4 * AIN);
            #pragma unroll
            for (int mm = 0; mm < 4; mm++) {
                ulonglong2 xA = xp[mm * 2];
                ulonglong2 xB = xp[mm * 2 + 1];
                FMA2(acc[mm], xA.x, wA.x);
                FMA2(acc[mm], xA.y, wA.y);
                FMA2(acc[mm], xB.x, wB.x);
                FMA2(acc[mm], xB.y, wB.y);
            }
        }
    }

    const float scale = 1.0f / 256.0f;
    float* dst = g_bpart + (size_t)blockIdx.y * (NK * MUL) + k * MUL + m0 + mi4 * 4;
    #pragma unroll
    for (int mm = 0; mm < 4; mm++) dst[mm] = pair_sum(acc[mm]) * scale;
}

// ---------------------------------------------------------------------------
// Softmax kernel: combine partials into b (optionally accumulating), softmax over m.
// ---------------------------------------------------------------------------
__global__ void __launch_bounds__(256)
softmax_kernel(int accum)
{
    const int k = blockIdx.x;
    const int t = threadIdx.x;
    const int lane = t & 31, wp = t >> 5;
    __shared__ float red[8];
    __shared__ float bc;

    float v[4];
    #pragma unroll
    for (int i = 0; i < 4; i++) {
        int m = t + i * 256;
        float b = accum ? g_b[k * MUL + m] : 0.f;
        #pragma unroll
        for (int p = 0; p < 8; p++) b += g_bpart[p * NK * MUL + k * MUL + m];
        g_b[k * MUL + m] = b;
        v[i] = b;
    }

    float mx = fmaxf(fmaxf(v[0], v[1]), fmaxf(v[2], v[3]));
    #pragma unroll
    for (int off = 16; off; off >>= 1)
        mx = fmaxf(mx, __shfl_xor_sync(0xffffffffu, mx, off));
    if (lane == 0) red[wp] = mx;
    __syncthreads();
    if (t == 0) {
        float m = red[0];
        #pragma unroll
        for (int i = 1; i < 8; i++) m = fmaxf(m, red[i]);
        bc = m;
    }
    __syncthreads();
    mx = bc;

    float s = 0.f;
    #pragma unroll
    for (int i = 0; i < 4; i++) { v[i] = expf(v[i] - mx); s += v[i]; }
    #pragma unroll
    for (int off = 16; off; off >>= 1)
        s += __shfl_xor_sync(0xffffffffu, s, off);
    __syncthreads();
    if (lane == 0) red[wp] = s;
    __syncthreads();
    if (t == 0) {
        float ss = 0.f;
        #pragma unroll
        for (int i = 0; i < 8; i++) ss += red[i];
        bc = ss;
    }
    __syncthreads();
    float inv = 1.0f / bc;
    float* c = g_c + k * MUL;
    #pragma unroll
    for (int i = 0; i < 4; i++) c[t + i * 256] = v[i] * inv;
}

// ---------------------------------------------------------------------------
extern "C" void kernel_launch(void* const* d_in, const int* in_sizes, int n_in,
                              void* d_out, int out_size)
{
    const float* x = (const float*)d_in[0];   // [256][1024][8] flat view
    const float* W = (const float*)d_in[1];   // [20][16][8]
    float* out = (float*)d_out;               // [256][20][16][1]

    dim3 ugrid(MUL / U_MT, 8);

    // prep: transpose x -> g_xt AND perform entire iteration-0 fused step
    prep_kernel<<<B_TOT, P_THREADS>>>(x, W);
    update_kernel<<<ugrid, U_THREADS>>>(x);
    softmax_kernel<<<NK, 256>>>(0);

    // iteration 1
    fused_kernel<<<B_TOT, F_THREADS>>>(W, out, 0);
    update_kernel<<<ugrid, U_THREADS>>>(x);
    softmax_kernel<<<NK, 256>>>(1);

    // iteration 2 (final -> write v)
    fused_kernel<<<B_TOT, F_THREADS>>>(W, out, 1);
}